// round 11
// baseline (speedup 1.0000x reference)
#include <cuda_runtime.h>
#include <cuda_fp16.h>
#include <cstdint>

#define Bb   256
#define Nn   128
#define Dd   2048
#define DH   128
#define Mtot (Bb*Nn)   // 32768

// W in MMA-fragment block layout: block(kb,nb) = 8n x 16k fp16, 256 B;
// lane l owns uint2{b0,b1} at [(kb*16+nb)*32 + l]. kb=k/16 (128), nb=n/8 (16).
__device__ __align__(256) uint2 g_wb[(size_t)128 * 16 * 32];   // 512 KB

__device__ __forceinline__ void mma16816(float* d, const uint32_t* a, uint32_t b0, uint32_t b1) {
    asm volatile(
        "mma.sync.aligned.m16n8k16.row.col.f32.f16.f16.f32 "
        "{%0,%1,%2,%3}, {%4,%5,%6,%7}, {%8,%9}, {%0,%1,%2,%3};"
        : "+f"(d[0]), "+f"(d[1]), "+f"(d[2]), "+f"(d[3])
        : "r"(a[0]), "r"(a[1]), "r"(a[2]), "r"(a[3]), "r"(b0), "r"(b1));
}
__device__ __forceinline__ float lrelu(float s) { return s > 0.f ? s : 0.2f * s; }

// ===================== config =====================
#define KC      32
#define NTILE   (Dd / KC)            // 64
#define AROW    80                   // padded fp16 row stride (bytes), 16B-aligned
#define TILE16  (128 * AROW)         // 10240 B per A fp16 buffer
#define SMEMSZ  (2 * TILE16)         // 20480 B

__global__ void __launch_bounds__(256, 2)
fused_gat(const float* __restrict__ X,
          const float* __restrict__ Wbv, const float* __restrict__ bbv,
          const float* __restrict__ Wcv, const float* __restrict__ bcv,
          const float* __restrict__ bias, float* __restrict__ out)
{
    extern __shared__ char smem[];
    const int tid = threadIdx.x;
    const int lane = tid & 31, w = tid >> 5;
    const int g = lane >> 2, tig = lane & 3;
    const int wm = w & 3;        // m-block (32 rows)
    const int wn = w >> 2;       // n-block (64 cols)

    float acc[2][8][4];
    #pragma unroll
    for (int mt = 0; mt < 2; mt++)
        #pragma unroll
        for (int nt = 0; nt < 8; nt++)
            #pragma unroll
            for (int q = 0; q < 4; q++) acc[mt][nt][q] = 0.f;

    // A load geometry: thread f (=tid+i*256) covers row f>>3, k-quad f&7 (float4).
    // Per warp: 4 rows x 128 B = 4 full lines per LDG.128 -> perfectly coalesced.
    const float* xbase = X + (size_t)blockIdx.x * 128 * Dd;
    const int arow = tid >> 3, akq = tid & 7;       // i-th chunk adds 32 rows

    // per-warp B base
    const uint2* wbase = g_wb + (size_t)(wn * 8) * 32 + lane;

    float4 xr[4];     // fp32 A for tile t+1 (in flight)
    // ---- prologue: xr = tile 0; STS tile 0 -> buf0; xr = tile 1 ----
    #pragma unroll
    for (int i = 0; i < 4; i++)
        xr[i] = *reinterpret_cast<const float4*>(xbase + (size_t)(arow + i * 32) * Dd + akq * 4);
    {
        char* bdst = smem;   // buf0
        #pragma unroll
        for (int i = 0; i < 4; i++) {
            __half2 h0 = __float22half2_rn(make_float2(xr[i].x, xr[i].y));
            __half2 h1 = __float22half2_rn(make_float2(xr[i].z, xr[i].w));
            *reinterpret_cast<uint2*>(bdst + (uint32_t)(arow + i * 32) * AROW + (uint32_t)akq * 8) =
                make_uint2(*reinterpret_cast<uint32_t*>(&h0), *reinterpret_cast<uint32_t*>(&h1));
        }
    }
    #pragma unroll
    for (int i = 0; i < 4; i++)
        xr[i] = *reinterpret_cast<const float4*>(xbase + (size_t)(arow + i * 32) * Dd + KC + akq * 4);
    __syncthreads();   // buf0 visible

    #pragma unroll 1
    for (int t = 0; t < NTILE; t++) {
        // ---- B frags for tile t (LDG early; land during STS below) ----
        uint2 bblk[2][8];
        #pragma unroll
        for (int s = 0; s < 2; s++)
            #pragma unroll
            for (int nt = 0; nt < 8; nt++)
                bblk[s][nt] = __ldg(wbase + (size_t)((t * 2 + s) * 16 + nt) * 32);

        // ---- STS tile t+1 (from xr) into buf((t+1)&1); then prefetch xr = tile t+2 ----
        // Safe: buf((t+1)&1) was last read by MMA(t-1); the sync ending iteration t-1
        // guarantees all warps are past it.
        if (t + 1 < NTILE) {
            char* bdst = smem + ((t + 1) & 1) * TILE16;
            #pragma unroll
            for (int i = 0; i < 4; i++) {
                __half2 h0 = __float22half2_rn(make_float2(xr[i].x, xr[i].y));
                __half2 h1 = __float22half2_rn(make_float2(xr[i].z, xr[i].w));
                *reinterpret_cast<uint2*>(bdst + (uint32_t)(arow + i * 32) * AROW + (uint32_t)akq * 8) =
                    make_uint2(*reinterpret_cast<uint32_t*>(&h0), *reinterpret_cast<uint32_t*>(&h1));
            }
            const int tn = (t + 2 < NTILE) ? t + 2 : t + 1;
            #pragma unroll
            for (int i = 0; i < 4; i++)
                xr[i] = *reinterpret_cast<const float4*>(
                    xbase + (size_t)(arow + i * 32) * Dd + (size_t)tn * KC + akq * 4);
        }

        // ---- MMA(t): A frags from buf(t&1) (written in iter t-1, visible via its sync) ----
        const char* abuf = smem + (t & 1) * TILE16;
        #pragma unroll
        for (int s = 0; s < 2; s++) {
            uint32_t ah[2][4];
            #pragma unroll
            for (int mt = 0; mt < 2; mt++) {
                const char* base = abuf + (wm * 32 + mt * 16 + g) * AROW + s * 32 + tig * 4;
                ah[mt][0] = *reinterpret_cast<const uint32_t*>(base);
                ah[mt][1] = *reinterpret_cast<const uint32_t*>(base + 8 * AROW);
                ah[mt][2] = *reinterpret_cast<const uint32_t*>(base + 16);
                ah[mt][3] = *reinterpret_cast<const uint32_t*>(base + 8 * AROW + 16);
            }
            #pragma unroll
            for (int nt = 0; nt < 8; nt++) {
                #pragma unroll
                for (int mt = 0; mt < 2; mt++)
                    mma16816(acc[mt][nt], ah[mt], bblk[s][nt].x, bblk[s][nt].y);
            }
        }
        __syncthreads();   // MMA(t) + STS(t+1) complete everywhere
    }

    // =============== fused epilogue: t1/t2, softmax(axis=i), output ===============
    float* eS1P = reinterpret_cast<float*>(smem);            // [128][2]
    float* eS2P = reinterpret_cast<float*>(smem + 1024);     // [128][2]
    float* eS1F = reinterpret_cast<float*>(smem + 2048);     // [128]
    float* eS2F = reinterpret_cast<float*>(smem + 2560);     // [128]
    float* eMX2 = reinterpret_cast<float*>(smem + 3072);     // [128][2]
    float* eZ2  = reinterpret_cast<float*>(smem + 4096);     // [128][2]
    float* eMX  = reinterpret_cast<float*>(smem + 5120);     // [128]
    float* eRZ  = reinterpret_cast<float*>(smem + 5632);     // [128]

    // (a) per-thread fragment dots with Wb/Wc
    float s1p[4] = {0.f, 0.f, 0.f, 0.f}, s2p[4] = {0.f, 0.f, 0.f, 0.f};
    #pragma unroll
    for (int nt = 0; nt < 8; nt++) {
        int c = wn * 64 + nt * 8 + 2 * tig;
        float wb0 = __ldg(Wbv + c), wb1 = __ldg(Wbv + c + 1);
        float wc0 = __ldg(Wcv + c), wc1 = __ldg(Wcv + c + 1);
        #pragma unroll
        for (int mt = 0; mt < 2; mt++) {
            s1p[mt * 2 + 0] += acc[mt][nt][0] * wb0 + acc[mt][nt][1] * wb1;
            s1p[mt * 2 + 1] += acc[mt][nt][2] * wb0 + acc[mt][nt][3] * wb1;
            s2p[mt * 2 + 0] += acc[mt][nt][0] * wc0 + acc[mt][nt][1] * wc1;
            s2p[mt * 2 + 1] += acc[mt][nt][2] * wc0 + acc[mt][nt][3] * wc1;
        }
    }
    // (b) reduce over tig
    #pragma unroll
    for (int off = 1; off <= 2; off <<= 1) {
        #pragma unroll
        for (int q = 0; q < 4; q++) {
            s1p[q] += __shfl_xor_sync(0xffffffffu, s1p[q], off);
            s2p[q] += __shfl_xor_sync(0xffffffffu, s2p[q], off);
        }
    }
    // (c) publish per-row partials per wn
    if (tig == 0) {
        #pragma unroll
        for (int q = 0; q < 4; q++) {
            int r = wm * 32 + (q >> 1) * 16 + (q & 1) * 8 + g;
            eS1P[r * 2 + wn] = s1p[q];
            eS2P[r * 2 + wn] = s2p[q];
        }
    }
    __syncthreads();
    // (d) finalize t1/t2
    if (tid < 128) {
        eS1F[tid] = eS1P[tid * 2] + eS1P[tid * 2 + 1] + bbv[0];
        eS2F[tid] = eS2P[tid * 2] + eS2P[tid * 2 + 1] + bcv[0];
    }
    __syncthreads();
    // (e) column softmax stats: 2 threads per column j
    {
        const int j = tid & 127, half = tid >> 7;
        const float s2j = eS2F[j];
        float m = -1e30f;
        #pragma unroll 4
        for (int i = half * 64; i < half * 64 + 64; i++)
            m = fmaxf(m, lrelu(eS1F[i] + s2j));
        eMX2[j * 2 + half] = m;
        __syncthreads();
        const float mj = fmaxf(eMX2[j * 2], eMX2[j * 2 + 1]);
        float z = 0.f;
        #pragma unroll 4
        for (int i = half * 64; i < half * 64 + 64; i++)
            z += __expf(lrelu(eS1F[i] + s2j) - mj);
        eZ2[j * 2 + half] = z;
        if (half == 0) eMX[j] = mj;
        __syncthreads();
        if (tid < 128) eRZ[tid] = 1.f / (eZ2[tid * 2] + eZ2[tid * 2 + 1]);
        __syncthreads();
    }
    // (f) output
    const size_t ob = (size_t)blockIdx.x * Nn * DH;
    float s1r[4];
    #pragma unroll
    for (int q = 0; q < 4; q++)
        s1r[q] = eS1F[wm * 32 + (q >> 1) * 16 + (q & 1) * 8 + g];
    #pragma unroll
    for (int nt = 0; nt < 8; nt++) {
        const int c = wn * 64 + nt * 8 + 2 * tig;
        const float s2a = eS2F[c],  s2b = eS2F[c + 1];
        const float mxa = eMX[c],   mxb = eMX[c + 1];
        const float rza = eRZ[c],   rzb = eRZ[c + 1];
        const float bia = __ldg(bias + c), bib = __ldg(bias + c + 1);
        #pragma unroll
        for (int mt = 0; mt < 2; mt++) {
            #pragma unroll
            for (int u = 0; u < 2; u++) {
                const int i = wm * 32 + mt * 16 + u * 8 + g;
                const float s1v = s1r[mt * 2 + u];
                const float ca = __expf(lrelu(s1v + s2a) - mxa) * rza;
                const float cb = __expf(lrelu(s1v + s2b) - mxb) * rzb;
                const float ha = acc[mt][nt][u * 2 + 0];
                const float hb = acc[mt][nt][u * 2 + 1];
                *reinterpret_cast<float2*>(&out[ob + (size_t)i * DH + c]) =
                    make_float2(fmaf(ca, ha, ha + bia), fmaf(cb, hb, hb + bib));
            }
        }
    }
}

// ===================== W -> fragment-block layout prep =====================
__global__ void wb_prep(const float* __restrict__ Wa)
{
    int t = blockIdx.x * 256 + threadIdx.x;     // 0 .. 65535
    int blk = t >> 5, l = t & 31;
    int kb = blk >> 4, nb = blk & 15;
    int n  = nb * 8 + (l >> 2);
    int k0 = kb * 16 + (l & 3) * 2;
    __half2 b0 = __floats2half2_rn(Wa[(size_t)k0 * DH + n],       Wa[(size_t)(k0 + 1) * DH + n]);
    __half2 b1 = __floats2half2_rn(Wa[(size_t)(k0 + 8) * DH + n], Wa[(size_t)(k0 + 9) * DH + n]);
    g_wb[(size_t)blk * 32 + l] = make_uint2(*reinterpret_cast<uint32_t*>(&b0),
                                            *reinterpret_cast<uint32_t*>(&b1));
}

// ===================== launch =====================
extern "C" void kernel_launch(void* const* d_in, const int* in_sizes, int n_in,
                              void* d_out, int out_size)
{
    const float* X    = (const float*)d_in[0];
    const float* Wa   = (const float*)d_in[1];
    const float* Wb   = (const float*)d_in[2];
    const float* bb   = (const float*)d_in[3];
    const float* Wc   = (const float*)d_in[4];
    const float* bc   = (const float*)d_in[5];
    const float* bias = (const float*)d_in[6];
    float* out = (float*)d_out;

    wb_prep<<<256, 256>>>(Wa);
    fused_gat<<<Bb, 256, SMEMSZ>>>(X, Wb, bb, Wc, bc, bias, out);
}

// round 12
// speedup vs baseline: 1.3282x; 1.3282x over previous
#include <cuda_runtime.h>
#include <cuda.h>
#include <cuda_fp16.h>
#include <cstdint>

#define Bb   256
#define Nn   128
#define Dd   2048
#define DH   128
#define Mtot (Bb*Nn)   // 32768

// W in MMA-fragment block layout: block(kb,nb) = 8n x 16k fp16, 256 B;
// lane l owns uint2{b0,b1} at [(kb*16+nb)*32 + l]. kb=k/16 (128), nb=n/8 (16).
__device__ __align__(256) uint2 g_wb[(size_t)128 * 16 * 32];   // 512 KB

// ===================== PTX helpers =====================
__device__ __forceinline__ uint32_t smem_u32(const void* p) {
    uint32_t a;
    asm("{ .reg .u64 t; cvta.to.shared.u64 t, %1; cvt.u32.u64 %0, t; }" : "=r"(a) : "l"(p));
    return a;
}
__device__ __forceinline__ void mbar_init(uint32_t m, uint32_t cnt) {
    asm volatile("mbarrier.init.shared.b64 [%0], %1;" :: "r"(m), "r"(cnt) : "memory");
}
__device__ __forceinline__ void mbar_expect_tx(uint32_t m, uint32_t bytes) {
    asm volatile("mbarrier.arrive.expect_tx.shared.b64 _, [%0], %1;" :: "r"(m), "r"(bytes) : "memory");
}
__device__ __forceinline__ void mbar_wait(uint32_t m, uint32_t ph) {
    asm volatile(
        "{\n\t.reg .pred P;\n"
        "W%=:\n\t"
        "mbarrier.try_wait.parity.acquire.cta.shared::cta.b64 P, [%0], %1, 0x989680;\n\t"
        "@P bra D%=;\n\t"
        "bra W%=;\n"
        "D%=:\n\t}"
        :: "r"(m), "r"(ph) : "memory");
}
__device__ __forceinline__ void tma2d(uint32_t dst, const CUtensorMap* map, int x, int y, uint32_t mbar) {
    asm volatile(
        "cp.async.bulk.tensor.2d.shared::cta.global.tile.mbarrier::complete_tx::bytes "
        "[%0], [%1, {%2, %3}], [%4];"
        :: "r"(dst), "l"(map), "r"(x), "r"(y), "r"(mbar) : "memory");
}
__device__ __forceinline__ void mma16816(float* d, const uint32_t* a, uint32_t b0, uint32_t b1) {
    asm volatile(
        "mma.sync.aligned.m16n8k16.row.col.f32.f16.f16.f32 "
        "{%0,%1,%2,%3}, {%4,%5,%6,%7}, {%8,%9}, {%0,%1,%2,%3};"
        : "+f"(d[0]), "+f"(d[1]), "+f"(d[2]), "+f"(d[3])
        : "r"(a[0]), "r"(a[1]), "r"(a[2]), "r"(a[3]), "r"(b0), "r"(b1));
}
__device__ __forceinline__ float lrelu(float s) { return s > 0.f ? s : 0.2f * s; }

// ===================== config =====================
#define KC        32
#define NTILE     (Dd / KC)               // 64
#define STAGES    4
#define FPA_STAGE (128 * KC * 4)          // 16384 B fp32 A tile
#define AROW      80                      // padded fp16 row stride, 16B-aligned, conflict-free
#define TILE16    (128 * AROW)            // 10240 B per fp16 A buffer
#define OFF_FPA   1024
#define OFF_AH    (OFF_FPA + STAGES * FPA_STAGE)   // 66560
#define SMEMSZ    (OFF_AH + 2 * TILE16)            // 87040 -> 2 CTAs/SM

__global__ void __launch_bounds__(256, 2)
fused_gat(const float* __restrict__ Wbv, const float* __restrict__ bbv,
          const float* __restrict__ Wcv, const float* __restrict__ bcv,
          const float* __restrict__ bias, float* __restrict__ out,
          const __grid_constant__ CUtensorMap mapA)
{
    extern __shared__ char smem[];
    const uint32_t sb = smem_u32(smem);
    const int tid = threadIdx.x;
    const int lane = tid & 31, w = tid >> 5;
    const int g = lane >> 2, tig = lane & 3;
    const int wm = w & 3;        // m-block (32 rows)
    const int wn = w >> 2;       // n-block (64 cols)

    if (tid == 0) {
        #pragma unroll
        for (int s = 0; s < STAGES; s++) mbar_init(sb + 8 * s, 1);
    }
    __syncthreads();
    if (tid == 0) {
        #pragma unroll
        for (int s = 0; s < STAGES; s++) {
            mbar_expect_tx(sb + 8 * s, FPA_STAGE);
            tma2d(sb + OFF_FPA + s * FPA_STAGE, &mapA, s * KC, blockIdx.x * 128, sb + 8 * s);
        }
    }

    float acc[2][8][4];
    #pragma unroll
    for (int mt = 0; mt < 2; mt++)
        #pragma unroll
        for (int nt = 0; nt < 8; nt++)
            #pragma unroll
            for (int q = 0; q < 4; q++) acc[mt][nt][q] = 0.f;

    // per-warp B base: blocks (kb*16 + wn*8 + nt), lane entry
    const uint2* wbase = g_wb + (size_t)(wn * 8) * 32 + lane;
    const int arow = tid >> 3, akq = tid & 7;   // A STS geometry (i-th chunk adds 32 rows)

    // ---- prologue: tile 0 -> buf0 ----
    {
        mbar_wait(sb + 0, 0);
        const float4* fa = reinterpret_cast<const float4*>(smem + OFF_FPA);
        #pragma unroll
        for (int i = 0; i < 4; i++) {
            float4 x = fa[tid + i * 256];
            __half2 h0 = __float22half2_rn(make_float2(x.x, x.y));
            __half2 h1 = __float22half2_rn(make_float2(x.z, x.w));
            *reinterpret_cast<uint2*>(smem + OFF_AH + (uint32_t)(arow + i * 32) * AROW +
                                      (uint32_t)akq * 8) =
                make_uint2(*reinterpret_cast<uint32_t*>(&h0), *reinterpret_cast<uint32_t*>(&h1));
        }
    }
    __syncthreads();   // buf0 visible; LDS(tile0) complete everywhere

    #pragma unroll 1
    for (int t = 0; t < NTILE; t++) {
        // TMA refill: stage t&3 (tile t consumed by all — entry/prologue sync) <- tile t+4
        if (tid == 0 && t + STAGES < NTILE) {
            mbar_expect_tx(sb + 8 * (t & 3), FPA_STAGE);
            tma2d(sb + OFF_FPA + (t & 3) * FPA_STAGE, &mapA,
                  (t + STAGES) * KC, blockIdx.x * 128, sb + 8 * (t & 3));
        }

        // B frags for tile t (LDG early; latency hidden under the prep below)
        uint2 bblk[2][8];
        #pragma unroll
        for (int s = 0; s < 2; s++)
            #pragma unroll
            for (int nt = 0; nt < 8; nt++)
                bblk[s][nt] = __ldg(wbase + (size_t)((t * 2 + s) * 16 + nt) * 32);

        // prepare tile t+1: wait stage, LDS fp32, cvt, STS into buf((t+1)&1)
        // (that buffer was last read by MMA(t-1); entry sync guarantees it's free)
        if (t + 1 < NTILE) {
            const int s2 = (t + 1) & (STAGES - 1);
            const uint32_t ph = ((t + 1) / STAGES) & 1;
            mbar_wait(sb + 8 * s2, ph);
            const float4* fa = reinterpret_cast<const float4*>(smem + OFF_FPA + s2 * FPA_STAGE);
            char* bdst = smem + OFF_AH + ((t + 1) & 1) * TILE16;
            #pragma unroll
            for (int i = 0; i < 4; i++) {
                float4 x = fa[tid + i * 256];
                __half2 h0 = __float22half2_rn(make_float2(x.x, x.y));
                __half2 h1 = __float22half2_rn(make_float2(x.z, x.w));
                *reinterpret_cast<uint2*>(bdst + (uint32_t)(arow + i * 32) * AROW +
                                          (uint32_t)akq * 8) =
                    make_uint2(*reinterpret_cast<uint32_t*>(&h0), *reinterpret_cast<uint32_t*>(&h1));
            }
        }

        // MMA(t): A frags from buf(t&1) (STS'd in iter t-1; visible via entry sync)
        const char* abuf = smem + OFF_AH + (t & 1) * TILE16;
        #pragma unroll
        for (int s = 0; s < 2; s++) {
            uint32_t ah[2][4];
            #pragma unroll
            for (int mt = 0; mt < 2; mt++) {
                const char* base = abuf + (wm * 32 + mt * 16 + g) * AROW + s * 32 + tig * 4;
                ah[mt][0] = *reinterpret_cast<const uint32_t*>(base);
                ah[mt][1] = *reinterpret_cast<const uint32_t*>(base + 8 * AROW);
                ah[mt][2] = *reinterpret_cast<const uint32_t*>(base + 16);
                ah[mt][3] = *reinterpret_cast<const uint32_t*>(base + 8 * AROW + 16);
            }
            #pragma unroll
            for (int nt = 0; nt < 8; nt++) {
                #pragma unroll
                for (int mt = 0; mt < 2; mt++)
                    mma16816(acc[mt][nt], ah[mt], bblk[s][nt].x, bblk[s][nt].y);
            }
        }
        __syncthreads();   // MMA(t) + STS(t+1) + LDS(t+1) complete everywhere
    }

    // =============== fused epilogue: t1/t2, softmax(axis=i), output ===============
    float* eS1P = reinterpret_cast<float*>(smem);            // [128][2]
    float* eS2P = reinterpret_cast<float*>(smem + 1024);     // [128][2]
    float* eS1F = reinterpret_cast<float*>(smem + 2048);     // [128]
    float* eS2F = reinterpret_cast<float*>(smem + 2560);     // [128]
    float* eMX2 = reinterpret_cast<float*>(smem + 3072);     // [128][2]
    float* eZ2  = reinterpret_cast<float*>(smem + 4096);     // [128][2]
    float* eMX  = reinterpret_cast<float*>(smem + 5120);     // [128]
    float* eRZ  = reinterpret_cast<float*>(smem + 5632);     // [128]

    // (a) per-thread fragment dots with Wb/Wc
    float s1p[4] = {0.f, 0.f, 0.f, 0.f}, s2p[4] = {0.f, 0.f, 0.f, 0.f};
    #pragma unroll
    for (int nt = 0; nt < 8; nt++) {
        int c = wn * 64 + nt * 8 + 2 * tig;
        float wb0 = __ldg(Wbv + c), wb1 = __ldg(Wbv + c + 1);
        float wc0 = __ldg(Wcv + c), wc1 = __ldg(Wcv + c + 1);
        #pragma unroll
        for (int mt = 0; mt < 2; mt++) {
            s1p[mt * 2 + 0] += acc[mt][nt][0] * wb0 + acc[mt][nt][1] * wb1;
            s1p[mt * 2 + 1] += acc[mt][nt][2] * wb0 + acc[mt][nt][3] * wb1;
            s2p[mt * 2 + 0] += acc[mt][nt][0] * wc0 + acc[mt][nt][1] * wc1;
            s2p[mt * 2 + 1] += acc[mt][nt][2] * wc0 + acc[mt][nt][3] * wc1;
        }
    }
    // (b) reduce over tig
    #pragma unroll
    for (int off = 1; off <= 2; off <<= 1) {
        #pragma unroll
        for (int q = 0; q < 4; q++) {
            s1p[q] += __shfl_xor_sync(0xffffffffu, s1p[q], off);
            s2p[q] += __shfl_xor_sync(0xffffffffu, s2p[q], off);
        }
    }
    // (c) publish per-row partials per wn
    if (tig == 0) {
        #pragma unroll
        for (int q = 0; q < 4; q++) {
            int r = wm * 32 + (q >> 1) * 16 + (q & 1) * 8 + g;
            eS1P[r * 2 + wn] = s1p[q];
            eS2P[r * 2 + wn] = s2p[q];
        }
    }
    __syncthreads();
    // (d) finalize t1/t2
    if (tid < 128) {
        eS1F[tid] = eS1P[tid * 2] + eS1P[tid * 2 + 1] + bbv[0];
        eS2F[tid] = eS2P[tid * 2] + eS2P[tid * 2 + 1] + bcv[0];
    }
    __syncthreads();
    // (e) column softmax stats: 2 threads per column j
    {
        const int j = tid & 127, half = tid >> 7;
        const float s2j = eS2F[j];
        float m = -1e30f;
        #pragma unroll 4
        for (int i = half * 64; i < half * 64 + 64; i++)
            m = fmaxf(m, lrelu(eS1F[i] + s2j));
        eMX2[j * 2 + half] = m;
        __syncthreads();
        const float mj = fmaxf(eMX2[j * 2], eMX2[j * 2 + 1]);
        float z = 0.f;
        #pragma unroll 4
        for (int i = half * 64; i < half * 64 + 64; i++)
            z += __expf(lrelu(eS1F[i] + s2j) - mj);
        eZ2[j * 2 + half] = z;
        if (half == 0) eMX[j] = mj;
        __syncthreads();
        if (tid < 128) eRZ[tid] = 1.f / (eZ2[tid * 2] + eZ2[tid * 2 + 1]);
        __syncthreads();
    }
    // (f) output
    const size_t ob = (size_t)blockIdx.x * Nn * DH;
    float s1r[4];
    #pragma unroll
    for (int q = 0; q < 4; q++)
        s1r[q] = eS1F[wm * 32 + (q >> 1) * 16 + (q & 1) * 8 + g];
    #pragma unroll
    for (int nt = 0; nt < 8; nt++) {
        const int c = wn * 64 + nt * 8 + 2 * tig;
        const float s2a = eS2F[c],  s2b = eS2F[c + 1];
        const float mxa = eMX[c],   mxb = eMX[c + 1];
        const float rza = eRZ[c],   rzb = eRZ[c + 1];
        const float bia = __ldg(bias + c), bib = __ldg(bias + c + 1);
        #pragma unroll
        for (int mt = 0; mt < 2; mt++) {
            #pragma unroll
            for (int u = 0; u < 2; u++) {
                const int i = wm * 32 + mt * 16 + u * 8 + g;
                const float s1v = s1r[mt * 2 + u];
                const float ca = __expf(lrelu(s1v + s2a) - mxa) * rza;
                const float cb = __expf(lrelu(s1v + s2b) - mxb) * rzb;
                const float ha = acc[mt][nt][u * 2 + 0];
                const float hb = acc[mt][nt][u * 2 + 1];
                *reinterpret_cast<float2*>(&out[ob + (size_t)i * DH + c]) =
                    make_float2(fmaf(ca, ha, ha + bia), fmaf(cb, hb, hb + bib));
            }
        }
    }
}

// ===================== W -> fragment-block layout prep =====================
__global__ void wb_prep(const float* __restrict__ Wa)
{
    int t = blockIdx.x * 256 + threadIdx.x;     // 0 .. 65535
    int blk = t >> 5, l = t & 31;
    int kb = blk >> 4, nb = blk & 15;
    int n  = nb * 8 + (l >> 2);
    int k0 = kb * 16 + (l & 3) * 2;
    __half2 b0 = __floats2half2_rn(Wa[(size_t)k0 * DH + n],       Wa[(size_t)(k0 + 1) * DH + n]);
    __half2 b1 = __floats2half2_rn(Wa[(size_t)(k0 + 8) * DH + n], Wa[(size_t)(k0 + 9) * DH + n]);
    g_wb[(size_t)blk * 32 + l] = make_uint2(*reinterpret_cast<uint32_t*>(&b0),
                                            *reinterpret_cast<uint32_t*>(&b1));
}

// ===================== launch =====================
typedef CUresult (*tmap_encode_t)(CUtensorMap*, CUtensorMapDataType, cuuint32_t, void*,
                                  const cuuint64_t*, const cuuint64_t*, const cuuint32_t*,
                                  const cuuint32_t*, CUtensorMapInterleave, CUtensorMapSwizzle,
                                  CUtensorMapL2promotion, CUtensorMapFloatOOBfill);

extern "C" void kernel_launch(void* const* d_in, const int* in_sizes, int n_in,
                              void* d_out, int out_size)
{
    const float* X    = (const float*)d_in[0];
    const float* Wa   = (const float*)d_in[1];
    const float* Wb   = (const float*)d_in[2];
    const float* bb   = (const float*)d_in[3];
    const float* Wc   = (const float*)d_in[4];
    const float* bc   = (const float*)d_in[5];
    const float* bias = (const float*)d_in[6];
    float* out = (float*)d_out;

    tmap_encode_t enc = nullptr;
    cudaDriverEntryPointQueryResult qr;
    cudaGetDriverEntryPointByVersion("cuTensorMapEncodeTiled", (void**)&enc, 12000,
                                     cudaEnableDefault, &qr);
    CUtensorMap mapA;
    {
        cuuint64_t dims[2]    = {Dd, Mtot};
        cuuint64_t strides[1] = {Dd * sizeof(float)};
        cuuint32_t box[2]     = {KC, 128};
        cuuint32_t es[2]      = {1, 1};
        enc(&mapA, CU_TENSOR_MAP_DATA_TYPE_FLOAT32, 2, (void*)X, dims, strides, box, es,
            CU_TENSOR_MAP_INTERLEAVE_NONE, CU_TENSOR_MAP_SWIZZLE_NONE,
            CU_TENSOR_MAP_L2_PROMOTION_L2_128B, CU_TENSOR_MAP_FLOAT_OOB_FILL_NONE);
    }

    wb_prep<<<256, 256>>>(Wa);

    cudaFuncSetAttribute(fused_gat, cudaFuncAttributeMaxDynamicSharedMemorySize, SMEMSZ);
    fused_gat<<<Bb, 256, SMEMSZ>>>(Wb, bb, Wc, bc, bias, out, mapA);
}

// round 13
// speedup vs baseline: 1.3412x; 1.0098x over previous
#include <cuda_runtime.h>
#include <cuda.h>
#include <cuda_fp16.h>
#include <cstdint>

#define Bb   256
#define Nn   128
#define Dd   2048
#define DH   128
#define Mtot (Bb*Nn)   // 32768

// W in MMA-fragment block layout: block(kb,nb) = 8n x 16k fp16, 256 B;
// lane l owns uint2{b0,b1} at [(kb*16+nb)*32 + l]. kb=k/16 (128), nb=n/8 (16).
__device__ __align__(256) uint2 g_wb[(size_t)128 * 16 * 32];   // 512 KB

// ===================== PTX helpers =====================
__device__ __forceinline__ uint32_t smem_u32(const void* p) {
    uint32_t a;
    asm("{ .reg .u64 t; cvta.to.shared.u64 t, %1; cvt.u32.u64 %0, t; }" : "=r"(a) : "l"(p));
    return a;
}
__device__ __forceinline__ void mbar_init(uint32_t m, uint32_t cnt) {
    asm volatile("mbarrier.init.shared.b64 [%0], %1;" :: "r"(m), "r"(cnt) : "memory");
}
__device__ __forceinline__ void mbar_expect_tx(uint32_t m, uint32_t bytes) {
    asm volatile("mbarrier.arrive.expect_tx.shared.b64 _, [%0], %1;" :: "r"(m), "r"(bytes) : "memory");
}
__device__ __forceinline__ void mbar_wait(uint32_t m, uint32_t ph) {
    asm volatile(
        "{\n\t.reg .pred P;\n"
        "W%=:\n\t"
        "mbarrier.try_wait.parity.acquire.cta.shared::cta.b64 P, [%0], %1, 0x989680;\n\t"
        "@P bra D%=;\n\t"
        "bra W%=;\n"
        "D%=:\n\t}"
        :: "r"(m), "r"(ph) : "memory");
}
__device__ __forceinline__ void tma2d(uint32_t dst, const CUtensorMap* map, int x, int y, uint32_t mbar) {
    asm volatile(
        "cp.async.bulk.tensor.2d.shared::cta.global.tile.mbarrier::complete_tx::bytes "
        "[%0], [%1, {%2, %3}], [%4];"
        :: "r"(dst), "l"(map), "r"(x), "r"(y), "r"(mbar) : "memory");
}
__device__ __forceinline__ void mma16816(float* d, const uint32_t* a, uint32_t b0, uint32_t b1) {
    asm volatile(
        "mma.sync.aligned.m16n8k16.row.col.f32.f16.f16.f32 "
        "{%0,%1,%2,%3}, {%4,%5,%6,%7}, {%8,%9}, {%0,%1,%2,%3};"
        : "+f"(d[0]), "+f"(d[1]), "+f"(d[2]), "+f"(d[3])
        : "r"(a[0]), "r"(a[1]), "r"(a[2]), "r"(a[3]), "r"(b0), "r"(b1));
}
__device__ __forceinline__ float lrelu(float s) { return s > 0.f ? s : 0.2f * s; }

// ===================== config =====================
#define KC        64
#define NTILE     (Dd / KC)               // 32
#define STAGES    2
#define FPA_STAGE (128 * KC * 4)          // 32768 B fp32 A tile
#define AROW      144                     // fp16 row stride: 128 B data + 16 pad (conflict-free)
#define TILE16    (128 * AROW)            // 18432 B per fp16 A buffer
#define OFF_FPA   1024
#define OFF_AH    (OFF_FPA + STAGES * FPA_STAGE)   // 66560
#define SMEMSZ    (OFF_AH + 2 * TILE16)            // 103424 -> 2 CTAs/SM

__global__ void __launch_bounds__(256, 2)
fused_gat(const float* __restrict__ Wbv, const float* __restrict__ bbv,
          const float* __restrict__ Wcv, const float* __restrict__ bcv,
          const float* __restrict__ bias, float* __restrict__ out,
          const __grid_constant__ CUtensorMap mapA)
{
    extern __shared__ char smem[];
    const uint32_t sb = smem_u32(smem);
    const int tid = threadIdx.x;
    const int lane = tid & 31, w = tid >> 5;
    const int g = lane >> 2, tig = lane & 3;
    const int wm = w & 3;        // m-block (32 rows)
    const int wn = w >> 2;       // n-block (64 cols)

    if (tid == 0) { mbar_init(sb + 0, 1); mbar_init(sb + 8, 1); }
    __syncthreads();
    if (tid == 0) {
        #pragma unroll
        for (int s = 0; s < STAGES; s++) {
            mbar_expect_tx(sb + 8 * s, FPA_STAGE);
            tma2d(sb + OFF_FPA + s * FPA_STAGE, &mapA, s * KC, blockIdx.x * 128, sb + 8 * s);
        }
    }

    float acc[2][8][4];
    #pragma unroll
    for (int mt = 0; mt < 2; mt++)
        #pragma unroll
        for (int nt = 0; nt < 8; nt++)
            #pragma unroll
            for (int q = 0; q < 4; q++) acc[mt][nt][q] = 0.f;

    // per-warp B base
    const uint2* wbase = g_wb + (size_t)(wn * 8) * 32 + lane;
    // A convert geometry: chunk f = tid + i*256 (i<8): row f>>4, 16B-quad f&15
    const int arow = tid >> 4, akq = tid & 15;   // each i adds 16 rows

    // ---- prologue: tile 0 -> buf0 ----
    {
        mbar_wait(sb + 0, 0);
        const float4* fa = reinterpret_cast<const float4*>(smem + OFF_FPA);
        #pragma unroll
        for (int i = 0; i < 8; i++) {
            float4 x = fa[tid + i * 256];
            __half2 h0 = __float22half2_rn(make_float2(x.x, x.y));
            __half2 h1 = __float22half2_rn(make_float2(x.z, x.w));
            *reinterpret_cast<uint2*>(smem + OFF_AH + (uint32_t)(arow + i * 16) * AROW +
                                      (uint32_t)akq * 8) =
                make_uint2(*reinterpret_cast<uint32_t*>(&h0), *reinterpret_cast<uint32_t*>(&h1));
        }
    }
    __syncthreads();   // buf0 visible; LDS(tile0) complete everywhere

    #pragma unroll 1
    for (int t = 0; t < NTILE; t++) {
        // TMA refill: stage t&1 (tile t consumed by all) <- tile t+2
        if (tid == 0 && t + 2 < NTILE) {
            mbar_expect_tx(sb + 8 * (t & 1), FPA_STAGE);
            tma2d(sb + OFF_FPA + (t & 1) * FPA_STAGE, &mapA,
                  (t + 2) * KC, blockIdx.x * 128, sb + 8 * (t & 1));
        }

        // B chunk 0: k16-steps 0,1 of tile t (latency hidden under prep below)
        uint2 bA[8], bB[8];
        #pragma unroll
        for (int nt = 0; nt < 8; nt++) {
            bA[nt] = __ldg(wbase + (size_t)((t * 4 + 0) * 16 + nt) * 32);
            bB[nt] = __ldg(wbase + (size_t)((t * 4 + 1) * 16 + nt) * 32);
        }

        // prepare tile t+1 into buf((t+1)&1) (freed by MMA(t-1); entry sync covers)
        if (t + 1 < NTILE) {
            const int s2 = (t + 1) & 1;
            const uint32_t ph = ((t + 1) >> 1) & 1;
            mbar_wait(sb + 8 * s2, ph);
            const float4* fa = reinterpret_cast<const float4*>(smem + OFF_FPA + s2 * FPA_STAGE);
            char* bdst = smem + OFF_AH + s2 * TILE16;
            #pragma unroll
            for (int i = 0; i < 8; i++) {
                float4 x = fa[tid + i * 256];
                __half2 h0 = __float22half2_rn(make_float2(x.x, x.y));
                __half2 h1 = __float22half2_rn(make_float2(x.z, x.w));
                *reinterpret_cast<uint2*>(bdst + (uint32_t)(arow + i * 16) * AROW +
                                          (uint32_t)akq * 8) =
                    make_uint2(*reinterpret_cast<uint32_t*>(&h0), *reinterpret_cast<uint32_t*>(&h1));
            }
        }

        // ---- MMA(t): 4 k16-steps, A frags from buf(t&1); B chunk1 loads interleaved ----
        const char* abuf = smem + OFF_AH + (t & 1) * TILE16;
        uint32_t ah[4][2][4];    // [s][mt][r]
        #pragma unroll
        for (int s = 0; s < 4; s++) {
            #pragma unroll
            for (int mt = 0; mt < 2; mt++) {
                const char* base = abuf + (wm * 32 + mt * 16 + g) * AROW + s * 32 + tig * 4;
                ah[s][mt][0] = *reinterpret_cast<const uint32_t*>(base);
                ah[s][mt][1] = *reinterpret_cast<const uint32_t*>(base + 8 * AROW);
                ah[s][mt][2] = *reinterpret_cast<const uint32_t*>(base + 16);
                ah[s][mt][3] = *reinterpret_cast<const uint32_t*>(base + 8 * AROW + 16);
            }
        }
        // s=0 (bA), then reload bA <- s=2
        #pragma unroll
        for (int nt = 0; nt < 8; nt++)
            #pragma unroll
            for (int mt = 0; mt < 2; mt++)
                mma16816(acc[mt][nt], ah[0][mt], bA[nt].x, bA[nt].y);
        #pragma unroll
        for (int nt = 0; nt < 8; nt++)
            bA[nt] = __ldg(wbase + (size_t)((t * 4 + 2) * 16 + nt) * 32);
        // s=1 (bB), then reload bB <- s=3
        #pragma unroll
        for (int nt = 0; nt < 8; nt++)
            #pragma unroll
            for (int mt = 0; mt < 2; mt++)
                mma16816(acc[mt][nt], ah[1][mt], bB[nt].x, bB[nt].y);
        #pragma unroll
        for (int nt = 0; nt < 8; nt++)
            bB[nt] = __ldg(wbase + (size_t)((t * 4 + 3) * 16 + nt) * 32);
        // s=2 (bA), s=3 (bB)
        #pragma unroll
        for (int nt = 0; nt < 8; nt++)
            #pragma unroll
            for (int mt = 0; mt < 2; mt++)
                mma16816(acc[mt][nt], ah[2][mt], bA[nt].x, bA[nt].y);
        #pragma unroll
        for (int nt = 0; nt < 8; nt++)
            #pragma unroll
            for (int mt = 0; mt < 2; mt++)
                mma16816(acc[mt][nt], ah[3][mt], bB[nt].x, bB[nt].y);

        __syncthreads();   // MMA(t) + STS(t+1) complete everywhere
    }

    // =============== fused epilogue: t1/t2, softmax(axis=i), output ===============
    float* eS1P = reinterpret_cast<float*>(smem);            // [128][2]
    float* eS2P = reinterpret_cast<float*>(smem + 1024);     // [128][2]
    float* eS1F = reinterpret_cast<float*>(smem + 2048);     // [128]
    float* eS2F = reinterpret_cast<float*>(smem + 2560);     // [128]
    float* eMX2 = reinterpret_cast<float*>(smem + 3072);     // [128][2]
    float* eZ2  = reinterpret_cast<float*>(smem + 4096);     // [128][2]
    float* eMX  = reinterpret_cast<float*>(smem + 5120);     // [128]
    float* eRZ  = reinterpret_cast<float*>(smem + 5632);     // [128]

    // (a) per-thread fragment dots with Wb/Wc
    float s1p[4] = {0.f, 0.f, 0.f, 0.f}, s2p[4] = {0.f, 0.f, 0.f, 0.f};
    #pragma unroll
    for (int nt = 0; nt < 8; nt++) {
        int c = wn * 64 + nt * 8 + 2 * tig;
        float wb0 = __ldg(Wbv + c), wb1 = __ldg(Wbv + c + 1);
        float wc0 = __ldg(Wcv + c), wc1 = __ldg(Wcv + c + 1);
        #pragma unroll
        for (int mt = 0; mt < 2; mt++) {
            s1p[mt * 2 + 0] += acc[mt][nt][0] * wb0 + acc[mt][nt][1] * wb1;
            s1p[mt * 2 + 1] += acc[mt][nt][2] * wb0 + acc[mt][nt][3] * wb1;
            s2p[mt * 2 + 0] += acc[mt][nt][0] * wc0 + acc[mt][nt][1] * wc1;
            s2p[mt * 2 + 1] += acc[mt][nt][2] * wc0 + acc[mt][nt][3] * wc1;
        }
    }
    // (b) reduce over tig
    #pragma unroll
    for (int off = 1; off <= 2; off <<= 1) {
        #pragma unroll
        for (int q = 0; q < 4; q++) {
            s1p[q] += __shfl_xor_sync(0xffffffffu, s1p[q], off);
            s2p[q] += __shfl_xor_sync(0xffffffffu, s2p[q], off);
        }
    }
    // (c) publish per-row partials per wn
    if (tig == 0) {
        #pragma unroll
        for (int q = 0; q < 4; q++) {
            int r = wm * 32 + (q >> 1) * 16 + (q & 1) * 8 + g;
            eS1P[r * 2 + wn] = s1p[q];
            eS2P[r * 2 + wn] = s2p[q];
        }
    }
    __syncthreads();
    // (d) finalize t1/t2
    if (tid < 128) {
        eS1F[tid] = eS1P[tid * 2] + eS1P[tid * 2 + 1] + bbv[0];
        eS2F[tid] = eS2P[tid * 2] + eS2P[tid * 2 + 1] + bcv[0];
    }
    __syncthreads();
    // (e) column softmax stats: 2 threads per column j
    {
        const int j = tid & 127, half = tid >> 7;
        const float s2j = eS2F[j];
        float m = -1e30f;
        #pragma unroll 4
        for (int i = half * 64; i < half * 64 + 64; i++)
            m = fmaxf(m, lrelu(eS1F[i] + s2j));
        eMX2[j * 2 + half] = m;
        __syncthreads();
        const float mj = fmaxf(eMX2[j * 2], eMX2[j * 2 + 1]);
        float z = 0.f;
        #pragma unroll 4
        for (int i = half * 64; i < half * 64 + 64; i++)
            z += __expf(lrelu(eS1F[i] + s2j) - mj);
        eZ2[j * 2 + half] = z;
        if (half == 0) eMX[j] = mj;
        __syncthreads();
        if (tid < 128) eRZ[tid] = 1.f / (eZ2[tid * 2] + eZ2[tid * 2 + 1]);
        __syncthreads();
    }
    // (f) output
    const size_t ob = (size_t)blockIdx.x * Nn * DH;
    float s1r[4];
    #pragma unroll
    for (int q = 0; q < 4; q++)
        s1r[q] = eS1F[wm * 32 + (q >> 1) * 16 + (q & 1) * 8 + g];
    #pragma unroll
    for (int nt = 0; nt < 8; nt++) {
        const int c = wn * 64 + nt * 8 + 2 * tig;
        const float s2a = eS2F[c],  s2b = eS2F[c + 1];
        const float mxa = eMX[c],   mxb = eMX[c + 1];
        const float rza = eRZ[c],   rzb = eRZ[c + 1];
        const float bia = __ldg(bias + c), bib = __ldg(bias + c + 1);
        #pragma unroll
        for (int mt = 0; mt < 2; mt++) {
            #pragma unroll
            for (int u = 0; u < 2; u++) {
                const int i = wm * 32 + mt * 16 + u * 8 + g;
                const float s1v = s1r[mt * 2 + u];
                const float ca = __expf(lrelu(s1v + s2a) - mxa) * rza;
                const float cb = __expf(lrelu(s1v + s2b) - mxb) * rzb;
                const float ha = acc[mt][nt][u * 2 + 0];
                const float hb = acc[mt][nt][u * 2 + 1];
                *reinterpret_cast<float2*>(&out[ob + (size_t)i * DH + c]) =
                    make_float2(fmaf(ca, ha, ha + bia), fmaf(cb, hb, hb + bib));
            }
        }
    }
}

// ===================== W -> fragment-block layout prep =====================
__global__ void wb_prep(const float* __restrict__ Wa)
{
    int t = blockIdx.x * 256 + threadIdx.x;     // 0 .. 65535
    int blk = t >> 5, l = t & 31;
    int kb = blk >> 4, nb = blk & 15;
    int n  = nb * 8 + (l >> 2);
    int k0 = kb * 16 + (l & 3) * 2;
    __half2 b0 = __floats2half2_rn(Wa[(size_t)k0 * DH + n],       Wa[(size_t)(k0 + 1) * DH + n]);
    __half2 b1 = __floats2half2_rn(Wa[(size_t)(k0 + 8) * DH + n], Wa[(size_t)(k0 + 9) * DH + n]);
    g_wb[(size_t)blk * 32 + l] = make_uint2(*reinterpret_cast<uint32_t*>(&b0),
                                            *reinterpret_cast<uint32_t*>(&b1));
}

// ===================== launch =====================
typedef CUresult (*tmap_encode_t)(CUtensorMap*, CUtensorMapDataType, cuuint32_t, void*,
                                  const cuuint64_t*, const cuuint64_t*, const cuuint32_t*,
                                  const cuuint32_t*, CUtensorMapInterleave, CUtensorMapSwizzle,
                                  CUtensorMapL2promotion, CUtensorMapFloatOOBfill);

extern "C" void kernel_launch(void* const* d_in, const int* in_sizes, int n_in,
                              void* d_out, int out_size)
{
    const float* X    = (const float*)d_in[0];
    const float* Wa   = (const float*)d_in[1];
    const float* Wb   = (const float*)d_in[2];
    const float* bb   = (const float*)d_in[3];
    const float* Wc   = (const float*)d_in[4];
    const float* bc   = (const float*)d_in[5];
    const float* bias = (const float*)d_in[6];
    float* out = (float*)d_out;

    tmap_encode_t enc = nullptr;
    cudaDriverEntryPointQueryResult qr;
    cudaGetDriverEntryPointByVersion("cuTensorMapEncodeTiled", (void**)&enc, 12000,
                                     cudaEnableDefault, &qr);
    CUtensorMap mapA;
    {
        cuuint64_t dims[2]    = {Dd, Mtot};
        cuuint64_t strides[1] = {Dd * sizeof(float)};
        cuuint32_t box[2]     = {KC, 128};
        cuuint32_t es[2]      = {1, 1};
        enc(&mapA, CU_TENSOR_MAP_DATA_TYPE_FLOAT32, 2, (void*)X, dims, strides, box, es,
            CU_TENSOR_MAP_INTERLEAVE_NONE, CU_TENSOR_MAP_SWIZZLE_NONE,
            CU_TENSOR_MAP_L2_PROMOTION_L2_128B, CU_TENSOR_MAP_FLOAT_OOB_FILL_NONE);
    }

    wb_prep<<<256, 256>>>(Wa);

    cudaFuncSetAttribute(fused_gat, cudaFuncAttributeMaxDynamicSharedMemorySize, SMEMSZ);
    fused_gat<<<Bb, 256, SMEMSZ>>>(Wb, bb, Wc, bc, bias, out, mapA);
}